// round 4
// baseline (speedup 1.0000x reference)
#include <cuda_runtime.h>
#include <math.h>

#define BATCH 4
#define SEQ   1024
#define EMB   1024
#define NH    16
#define HD    64
#define M_TOT (BATCH*SEQ)          // 4096
#define INV_DENOM (1.0f/32.0f)     // 1/sqrt(EMB_DIM)

// Scratch (allocation-free: __device__ globals)
static __device__ float g_QA[BATCH*NH*SEQ*128];  // [b,h,s, 0:64]=(Q+P)/32, [64:128]=Im/32
static __device__ float g_KA[BATCH*NH*SEQ*128];  // [b,h,s, 0:64]=(K+P),   [64:128]=Im
static __device__ float g_V [BATCH*NH*SEQ*HD];   // [b,h,s,d] = (V+P)
static __device__ float g_O [M_TOT*EMB];         // merged-head attention output [b*S+s, h*64+d]

// ---------------------------------------------------------------------------
// SGEMM: C = A[4096x1024] @ B[1024x1024], templated epilogue
// MODE 0: Q proj -> g_QA (bias + pos, *1/32)
// MODE 1: K proj -> g_KA (bias + pos)
// MODE 2: V proj -> g_V  (bias + pos)
// MODE 3: out    -> Out  (A := g_O, bias only)
// ---------------------------------------------------------------------------
template<int MODE>
__global__ void __launch_bounds__(256, 2) sgemm_kernel(
    const float* __restrict__ A, const float* __restrict__ Bm,
    const float* __restrict__ bias, const float* __restrict__ pos,
    float* __restrict__ Out)
{
    __shared__ float As[8][132];   // k-major, pad to reduce STS conflicts
    __shared__ float Bs[8][128];

    const float* Ain = (MODE == 3) ? g_O : A;
    const int t  = threadIdx.x;
    const int m0 = blockIdx.y * 128;
    const int n0 = blockIdx.x * 128;
    const int tr = t >> 4, tc = t & 15;

    float acc[8][8];
#pragma unroll
    for (int i = 0; i < 8; ++i)
#pragma unroll
        for (int j = 0; j < 8; ++j) acc[i][j] = 0.f;

    const int ar = t >> 1, ac4 = (t & 1) * 4;   // A tile: 128 rows x 8 k
    const int br = t >> 5, bc4 = (t & 31) * 4;  // B tile: 8 k x 128 cols
    const float* Ap = Ain + (size_t)(m0 + ar) * EMB + ac4;
    const float* Bp = Bm  + (size_t)br * EMB + n0 + bc4;

    for (int k0 = 0; k0 < EMB; k0 += 8) {
        float4 av = *(const float4*)(Ap + k0);
        float4 bv = *(const float4*)(Bp + (size_t)k0 * EMB);
        __syncthreads();
        As[ac4 + 0][ar] = av.x; As[ac4 + 1][ar] = av.y;
        As[ac4 + 2][ar] = av.z; As[ac4 + 3][ar] = av.w;
        *(float4*)&Bs[br][bc4] = bv;
        __syncthreads();
#pragma unroll
        for (int kk = 0; kk < 8; ++kk) {
            float a[8], b[8];
            float4 a0 = *(const float4*)&As[kk][tr * 8];
            float4 a1 = *(const float4*)&As[kk][tr * 8 + 4];
            float4 b0 = *(const float4*)&Bs[kk][tc * 8];
            float4 b1 = *(const float4*)&Bs[kk][tc * 8 + 4];
            a[0]=a0.x; a[1]=a0.y; a[2]=a0.z; a[3]=a0.w;
            a[4]=a1.x; a[5]=a1.y; a[6]=a1.z; a[7]=a1.w;
            b[0]=b0.x; b[1]=b0.y; b[2]=b0.z; b[3]=b0.w;
            b[4]=b1.x; b[5]=b1.y; b[6]=b1.z; b[7]=b1.w;
#pragma unroll
            for (int i = 0; i < 8; ++i)
#pragma unroll
                for (int j = 0; j < 8; ++j)
                    acc[i][j] += a[i] * b[j];
        }
    }

    // Epilogue
#pragma unroll
    for (int i = 0; i < 8; ++i) {
        const int row = m0 + tr * 8 + i;           // row = b*SEQ + s
        const int bb  = row >> 10;
        const int ss  = row & 1023;
#pragma unroll
        for (int j = 0; j < 8; ++j) {
            const int col = n0 + tc * 8 + j;
            float v = acc[i][j] + bias[col];
            if (MODE <= 2) {
                const int h = col >> 6, d = col & 63;
                v += pos[(size_t)row * HD + d];
                const size_t hs = (size_t)((bb * NH + h) * SEQ + ss);
                if (MODE == 0)      g_QA[hs * 128 + d] = v * INV_DENOM;
                else if (MODE == 1) g_KA[hs * 128 + d] = v;
                else                g_V [hs * HD  + d] = v;
            } else {
                Out[(size_t)row * EMB + col] = v;
            }
        }
    }
}

// ---------------------------------------------------------------------------
// Fill Im halves of augmented Q/K buffers
// ---------------------------------------------------------------------------
__global__ void im_fill_kernel(const float* __restrict__ Im)
{
    int i = blockIdx.x * 256 + threadIdx.x;      // i < 2^20 (float4 units)
    int d4 = (i & 15) * 4;
    int s  = (i >> 4) & 1023;
    int h  = (i >> 14) & 15;
    int b  = i >> 18;
    float4 v = *(const float4*)&Im[((size_t)(b * SEQ + s)) * EMB + h * HD + d4];
    size_t o = ((size_t)((b * NH + h) * SEQ + s)) * 128 + 64 + d4;
    float4 q = make_float4(v.x * INV_DENOM, v.y * INV_DENOM,
                           v.z * INV_DENOM, v.w * INV_DENOM);
    *(float4*)&g_QA[o] = q;
    *(float4*)&g_KA[o] = v;
}

// ---------------------------------------------------------------------------
// Flash-style attention: 64 queries x 64 keys per tile, augmented D=128.
// 256 threads = 16x16, each 4x4. Online softmax (shuffle over tx group).
// ---------------------------------------------------------------------------
__global__ void __launch_bounds__(256, 2) attn_kernel()
{
    extern __shared__ float sm[];
    float* Qs = sm;                    // [64][129]
    float* Ks = Qs + 64 * 129;         // [64][129]
    float* Vs = Ks + 64 * 129;         // [64][64]
    float* Ps = Vs + 64 * 64;          // [64][68]

    const int t  = threadIdx.x;
    const int qt = blockIdx.x;         // query tile 0..15
    const int h  = blockIdx.y;
    const int b  = blockIdx.z;
    const size_t head = (size_t)(b * NH + h);
    const float* Qg = g_QA + head * SEQ * 128 + (size_t)qt * 64 * 128;
    const float* Kg = g_KA + head * SEQ * 128;
    const float* Vg = g_V  + head * SEQ * HD;

    // Load Q tile (64 x 128)
#pragma unroll
    for (int i = 0; i < 8; ++i) {
        int f = t + i * 256;           // float4 index 0..2047
        int r = f >> 5, d = (f & 31) * 4;
        float4 v = *(const float4*)(Qg + r * 128 + d);
        float* dst = Qs + r * 129 + d;
        dst[0] = v.x; dst[1] = v.y; dst[2] = v.z; dst[3] = v.w;
    }

    const int ty = t >> 4, tx = t & 15;
    float m_i[4], l_i[4], o[4][4];
#pragma unroll
    for (int i = 0; i < 4; ++i) {
        m_i[i] = -1e30f; l_i[i] = 0.f;
#pragma unroll
        for (int j = 0; j < 4; ++j) o[i][j] = 0.f;
    }

    for (int kt = 0; kt < 16; ++kt) {
        __syncthreads();               // prev P@V done; Q visible on kt==0
        // Load K tile (64 x 128) and V tile (64 x 64)
#pragma unroll
        for (int i = 0; i < 8; ++i) {
            int f = t + i * 256;
            int r = f >> 5, d = (f & 31) * 4;
            float4 v = *(const float4*)(Kg + (size_t)(kt * 64 + r) * 128 + d);
            float* dst = Ks + r * 129 + d;
            dst[0] = v.x; dst[1] = v.y; dst[2] = v.z; dst[3] = v.w;
        }
#pragma unroll
        for (int i = 0; i < 4; ++i) {
            int f = t + i * 256;
            int r = f >> 4, d = (f & 15) * 4;
            *(float4*)(Vs + r * 64 + d) =
                *(const float4*)(Vg + (size_t)(kt * 64 + r) * HD + d);
        }
        __syncthreads();

        // S = Q K^T over augmented d=128
        float s[4][4];
#pragma unroll
        for (int i = 0; i < 4; ++i)
#pragma unroll
            for (int j = 0; j < 4; ++j) s[i][j] = 0.f;
#pragma unroll 4
        for (int d = 0; d < 128; ++d) {
            float qv[4], kv[4];
#pragma unroll
            for (int i = 0; i < 4; ++i) qv[i] = Qs[(ty * 4 + i) * 129 + d];
#pragma unroll
            for (int j = 0; j < 4; ++j) kv[j] = Ks[(tx * 4 + j) * 129 + d];
#pragma unroll
            for (int i = 0; i < 4; ++i)
#pragma unroll
                for (int j = 0; j < 4; ++j)
                    s[i][j] += qv[i] * kv[j];
        }

        // Online softmax per row (reduce across 16-lane tx group)
#pragma unroll
        for (int i = 0; i < 4; ++i) {
            float mx = fmaxf(fmaxf(s[i][0], s[i][1]), fmaxf(s[i][2], s[i][3]));
#pragma unroll
            for (int off = 8; off; off >>= 1)
                mx = fmaxf(mx, __shfl_xor_sync(0xffffffffu, mx, off));
            float mnew  = fmaxf(m_i[i], mx);
            float scale = __expf(m_i[i] - mnew);
            float rs = 0.f;
#pragma unroll
            for (int j = 0; j < 4; ++j) {
                s[i][j] = __expf(s[i][j] - mnew);
                rs += s[i][j];
            }
#pragma unroll
            for (int off = 8; off; off >>= 1)
                rs += __shfl_xor_sync(0xffffffffu, rs, off);
            l_i[i] = l_i[i] * scale + rs;
            m_i[i] = mnew;
#pragma unroll
            for (int j = 0; j < 4; ++j) o[i][j] *= scale;
            *(float4*)(Ps + (ty * 4 + i) * 68 + tx * 4) =
                make_float4(s[i][0], s[i][1], s[i][2], s[i][3]);
        }
        __syncthreads();

        // O += P @ V
#pragma unroll 4
        for (int c = 0; c < 64; ++c) {
            float pv[4], vv[4];
#pragma unroll
            for (int i = 0; i < 4; ++i) pv[i] = Ps[(ty * 4 + i) * 68 + c];
#pragma unroll
            for (int j = 0; j < 4; ++j) vv[j] = Vs[c * 64 + tx * 4 + j];
#pragma unroll
            for (int i = 0; i < 4; ++i)
#pragma unroll
                for (int j = 0; j < 4; ++j)
                    o[i][j] += pv[i] * vv[j];
        }
    }

    // Normalize, write merged-head layout
#pragma unroll
    for (int i = 0; i < 4; ++i) {
        int q = qt * 64 + ty * 4 + i;
        float inv = 1.f / l_i[i];
        float4 v = make_float4(o[i][0] * inv, o[i][1] * inv,
                               o[i][2] * inv, o[i][3] * inv);
        *(float4*)(g_O + ((size_t)(b * SEQ + q)) * EMB + h * HD + tx * 4) = v;
    }
}

// ---------------------------------------------------------------------------
extern "C" void kernel_launch(void* const* d_in, const int* in_sizes, int n_in,
                              void* d_out, int out_size)
{
    const float* Re  = (const float*)d_in[0];
    const float* Im  = (const float*)d_in[1];
    const float* pos = (const float*)d_in[2];
    const float* Wq  = (const float*)d_in[3];
    const float* bq  = (const float*)d_in[4];
    const float* Wk  = (const float*)d_in[5];
    const float* bk  = (const float*)d_in[6];
    const float* Wv  = (const float*)d_in[7];
    const float* bv  = (const float*)d_in[8];
    const float* Wo  = (const float*)d_in[9];
    const float* bo  = (const float*)d_in[10];
    float* out = (float*)d_out;

    const dim3 gg(EMB / 128, M_TOT / 128);   // (8, 32)

    sgemm_kernel<0><<<gg, 256>>>(Re, Wq, bq, pos, nullptr);
    sgemm_kernel<1><<<gg, 256>>>(Re, Wk, bk, pos, nullptr);
    sgemm_kernel<2><<<gg, 256>>>(Re, Wv, bv, pos, nullptr);
    im_fill_kernel<<<4096, 256>>>(Im);

    const int attn_smem = (2 * 64 * 129 + 64 * 64 + 64 * 68) * (int)sizeof(float); // 99840
    cudaFuncSetAttribute(attn_kernel,
                         cudaFuncAttributeMaxDynamicSharedMemorySize, attn_smem);
    attn_kernel<<<dim3(16, NH, BATCH), 256, attn_smem>>>();

    sgemm_kernel<3><<<gg, 256>>>(Re /*unused*/, Wo, bo, nullptr, out);
}

// round 5
// speedup vs baseline: 1.5302x; 1.5302x over previous
#include <cuda_runtime.h>
#include <cstdint>
#include <math.h>

#define BATCH 4
#define SEQ   1024
#define EMB   1024
#define NH    16
#define HD    64
#define M_TOT (BATCH*SEQ)          // 4096
#define INV_DENOM (1.0f/32.0f)     // 1/sqrt(EMB_DIM)

// Scratch (allocation-free: __device__ globals)
static __device__ float g_QA[BATCH*NH*SEQ*128];  // [b,h,s, 0:64]=(Q+P)/32, [64:128]=Im/32
static __device__ float g_KA[BATCH*NH*SEQ*128];  // [b,h,s, 0:64]=(K+P),   [64:128]=Im
static __device__ float g_V [BATCH*NH*SEQ*HD];   // [b,h,s,d] = (V+P)
static __device__ float g_O [M_TOT*EMB];         // merged-head attention output

// ---------------------------------------------------------------------------
// tf32 helpers
// ---------------------------------------------------------------------------
__device__ __forceinline__ uint32_t f2tf32(float f) {
    uint32_t u;
    asm("cvt.rna.tf32.f32 %0, %1;" : "=r"(u) : "f"(f));
    return u;
}

__device__ __forceinline__ void mma_tf32(float c[4], const uint32_t a[4],
                                         const uint32_t b[2]) {
    asm volatile(
        "mma.sync.aligned.m16n8k8.row.col.f32.tf32.tf32.f32 "
        "{%0,%1,%2,%3}, {%4,%5,%6,%7}, {%8,%9}, {%0,%1,%2,%3};"
        : "+f"(c[0]), "+f"(c[1]), "+f"(c[2]), "+f"(c[3])
        : "r"(a[0]), "r"(a[1]), "r"(a[2]), "r"(a[3]), "r"(b[0]), "r"(b[1]));
}

__device__ __forceinline__ void cp16(float* dst, const float* src) {
    uint32_t d = (uint32_t)__cvta_generic_to_shared(dst);
    asm volatile("cp.async.cg.shared.global [%0], [%1], 16;" :: "r"(d), "l"(src));
}

// ---------------------------------------------------------------------------
// TF32 GEMM: C = A[4096x1024] @ B[1024x1024], templated epilogue.
// CTA tile 128x128x32, 8 warps (2m x 4n), warp tile 64x32, m16n8k8 MMA.
// Smem: A[128][36] (pad->bank-free frags), B[32][136]. 2-stage cp.async.
// MODE 0: Q proj -> g_QA (bias+pos, *1/32)   MODE 1: K proj -> g_KA (bias+pos)
// MODE 2: V proj -> g_V  (bias+pos)          MODE 3: A:=g_O -> Out (bias)
// ---------------------------------------------------------------------------
#define AS_STRIDE 36
#define BS_STRIDE 136
#define AS_WORDS  (128*AS_STRIDE)   // 4608
#define BS_WORDS  (32*BS_STRIDE)    // 4352
#define GEMM_SMEM ((2*AS_WORDS + 2*BS_WORDS)*4)   // 71680 bytes

template<int MODE>
__device__ __forceinline__ void gemm_store(int row, int col, float v,
    const float* __restrict__ bias, const float* __restrict__ pos,
    float* __restrict__ Out)
{
    v += bias[col];
    if (MODE <= 2) {
        const int bb = row >> 10, ss = row & 1023;
        const int h = col >> 6, d = col & 63;
        v += pos[(size_t)row * HD + d];
        const size_t hs = (size_t)((bb * NH + h) * SEQ + ss);
        if (MODE == 0)      g_QA[hs * 128 + d] = v * INV_DENOM;
        else if (MODE == 1) g_KA[hs * 128 + d] = v;
        else                g_V [hs * HD  + d] = v;
    } else {
        Out[(size_t)row * EMB + col] = v;
    }
}

template<int MODE>
__device__ __forceinline__ void issue_tile(
    const float* __restrict__ A, const float* __restrict__ Bm,
    float* as, float* bs, int t, int m0, int n0, int k0)
{
#pragma unroll
    for (int i = 0; i < 4; ++i) {
        int f = t + i * 256;
        int row = f >> 3, kc = (f & 7) * 4;
        cp16(as + row * AS_STRIDE + kc, A + (size_t)(m0 + row) * EMB + k0 + kc);
    }
#pragma unroll
    for (int i = 0; i < 4; ++i) {
        int f = t + i * 256;
        int k = f >> 5, nc = (f & 31) * 4;
        cp16(bs + k * BS_STRIDE + nc, Bm + (size_t)(k0 + k) * EMB + n0 + nc);
    }
    asm volatile("cp.async.commit_group;");
}

template<int MODE>
__global__ void __launch_bounds__(256, 2) gemm_tf32(
    const float* __restrict__ A, const float* __restrict__ Bm,
    const float* __restrict__ bias, const float* __restrict__ pos,
    float* __restrict__ Out)
{
    extern __shared__ float sm[];
    float* Asb[2] = { sm, sm + AS_WORDS };
    float* Bsb[2] = { sm + 2 * AS_WORDS, sm + 2 * AS_WORDS + BS_WORDS };

    const float* Ain = (MODE == 3) ? g_O : A;
    const int t    = threadIdx.x;
    const int m0   = blockIdx.y * 128;
    const int n0   = blockIdx.x * 128;
    const int lane = t & 31, warp = t >> 5;
    const int wm = warp >> 2, wn = warp & 3;

    float acc[4][4][4];
#pragma unroll
    for (int mf = 0; mf < 4; ++mf)
#pragma unroll
        for (int nf = 0; nf < 4; ++nf)
#pragma unroll
            for (int j = 0; j < 4; ++j) acc[mf][nf][j] = 0.f;

    issue_tile<MODE>(Ain, Bm, Asb[0], Bsb[0], t, m0, n0, 0);

    int cur = 0;
    for (int k0 = 0; k0 < EMB; k0 += 32) {
        const bool more = (k0 + 32 < EMB);
        if (more) {
            issue_tile<MODE>(Ain, Bm, Asb[cur ^ 1], Bsb[cur ^ 1], t, m0, n0, k0 + 32);
            asm volatile("cp.async.wait_group 1;");
        } else {
            asm volatile("cp.async.wait_group 0;");
        }
        __syncthreads();

        const float* as = Asb[cur];
        const float* bs = Bsb[cur];
#pragma unroll
        for (int kk = 0; kk < 32; kk += 8) {
            uint32_t a[4][4], b[4][2];
#pragma unroll
            for (int mf = 0; mf < 4; ++mf) {
                const float* p = as + (wm * 64 + mf * 16 + (lane >> 2)) * AS_STRIDE
                                    + kk + (lane & 3);
                a[mf][0] = f2tf32(p[0]);
                a[mf][1] = f2tf32(p[8 * AS_STRIDE]);
                a[mf][2] = f2tf32(p[4]);
                a[mf][3] = f2tf32(p[8 * AS_STRIDE + 4]);
            }
#pragma unroll
            for (int nf = 0; nf < 4; ++nf) {
                const float* p = bs + (kk + (lane & 3)) * BS_STRIDE
                                    + wn * 32 + nf * 8 + (lane >> 2);
                b[nf][0] = f2tf32(p[0]);
                b[nf][1] = f2tf32(p[4 * BS_STRIDE]);
            }
#pragma unroll
            for (int mf = 0; mf < 4; ++mf)
#pragma unroll
                for (int nf = 0; nf < 4; ++nf)
                    mma_tf32(acc[mf][nf], a[mf], b[nf]);
        }
        __syncthreads();
        cur ^= 1;
    }

    // Epilogue: fragment layout m16n8 -> (row, col)
#pragma unroll
    for (int mf = 0; mf < 4; ++mf) {
        const int r0 = m0 + wm * 64 + mf * 16 + (lane >> 2);
#pragma unroll
        for (int nf = 0; nf < 4; ++nf) {
            const int c0 = n0 + wn * 32 + nf * 8 + (lane & 3) * 2;
            gemm_store<MODE>(r0,     c0,     acc[mf][nf][0], bias, pos, Out);
            gemm_store<MODE>(r0,     c0 + 1, acc[mf][nf][1], bias, pos, Out);
            gemm_store<MODE>(r0 + 8, c0,     acc[mf][nf][2], bias, pos, Out);
            gemm_store<MODE>(r0 + 8, c0 + 1, acc[mf][nf][3], bias, pos, Out);
        }
    }
}

// ---------------------------------------------------------------------------
// Fill Im halves of augmented Q/K buffers
// ---------------------------------------------------------------------------
__global__ void im_fill_kernel(const float* __restrict__ Im)
{
    int i = blockIdx.x * 256 + threadIdx.x;      // i < 2^20 (float4 units)
    int d4 = (i & 15) * 4;
    int s  = (i >> 4) & 1023;
    int h  = (i >> 14) & 15;
    int b  = i >> 18;
    float4 v = *(const float4*)&Im[((size_t)(b * SEQ + s)) * EMB + h * HD + d4];
    size_t o = ((size_t)((b * NH + h) * SEQ + s)) * 128 + 64 + d4;
    float4 q = make_float4(v.x * INV_DENOM, v.y * INV_DENOM,
                           v.z * INV_DENOM, v.w * INV_DENOM);
    *(float4*)&g_QA[o] = q;
    *(float4*)&g_KA[o] = v;
}

// ---------------------------------------------------------------------------
// Flash-style attention (fp32 FFMA, unchanged from passing R3 kernel)
// ---------------------------------------------------------------------------
__global__ void __launch_bounds__(256, 2) attn_kernel()
{
    extern __shared__ float smatt[];
    float* Qs = smatt;                 // [64][129]
    float* Ks = Qs + 64 * 129;         // [64][129]
    float* Vs = Ks + 64 * 129;         // [64][64]
    float* Ps = Vs + 64 * 64;          // [64][68]

    const int t  = threadIdx.x;
    const int qt = blockIdx.x;
    const int h  = blockIdx.y;
    const int b  = blockIdx.z;
    const size_t head = (size_t)(b * NH + h);
    const float* Qg = g_QA + head * SEQ * 128 + (size_t)qt * 64 * 128;
    const float* Kg = g_KA + head * SEQ * 128;
    const float* Vg = g_V  + head * SEQ * HD;

#pragma unroll
    for (int i = 0; i < 8; ++i) {
        int f = t + i * 256;
        int r = f >> 5, d = (f & 31) * 4;
        float4 v = *(const float4*)(Qg + r * 128 + d);
        float* dst = Qs + r * 129 + d;
        dst[0] = v.x; dst[1] = v.y; dst[2] = v.z; dst[3] = v.w;
    }

    const int ty = t >> 4, tx = t & 15;
    float m_i[4], l_i[4], o[4][4];
#pragma unroll
    for (int i = 0; i < 4; ++i) {
        m_i[i] = -1e30f; l_i[i] = 0.f;
#pragma unroll
        for (int j = 0; j < 4; ++j) o[i][j] = 0.f;
    }

    for (int kt = 0; kt < 16; ++kt) {
        __syncthreads();
#pragma unroll
        for (int i = 0; i < 8; ++i) {
            int f = t + i * 256;
            int r = f >> 5, d = (f & 31) * 4;
            float4 v = *(const float4*)(Kg + (size_t)(kt * 64 + r) * 128 + d);
            float* dst = Ks + r * 129 + d;
            dst[0] = v.x; dst[1] = v.y; dst[2] = v.z; dst[3] = v.w;
        }
#pragma unroll
        for (int i = 0; i < 4; ++i) {
            int f = t + i * 256;
            int r = f >> 4, d = (f & 15) * 4;
            *(float4*)(Vs + r * 64 + d) =
                *(const float4*)(Vg + (size_t)(kt * 64 + r) * HD + d);
        }
        __syncthreads();

        float s[4][4];
#pragma unroll
        for (int i = 0; i < 4; ++i)
#pragma unroll
            for (int j = 0; j < 4; ++j) s[i][j] = 0.f;
#pragma unroll 4
        for (int d = 0; d < 128; ++d) {
            float qv[4], kv[4];
#pragma unroll
            for (int i = 0; i < 4; ++i) qv[i] = Qs[(ty * 4 + i) * 129 + d];
#pragma unroll
            for (int j = 0; j < 4; ++j) kv[j] = Ks[(tx * 4 + j) * 129 + d];
#pragma unroll
            for (int i = 0; i < 4; ++i)
#pragma unroll
                for (int j = 0; j < 4; ++j)
                    s[i][j] += qv[i] * kv[j];
        }

#pragma unroll
        for (int i = 0; i < 4; ++i) {
            float mx = fmaxf(fmaxf(s[i][0], s[i][1]), fmaxf(s[i][2], s[i][3]));
#pragma unroll
            for (int off = 8; off; off >>= 1)
                mx = fmaxf(mx, __shfl_xor_sync(0xffffffffu, mx, off));
            float mnew  = fmaxf(m_i[i], mx);
            float scale = __expf(m_i[i] - mnew);
            float rs = 0.f;
#pragma unroll
            for (int j = 0; j < 4; ++j) {
                s[i][j] = __expf(s[i][j] - mnew);
                rs += s[i][j];
            }
#pragma unroll
            for (int off = 8; off; off >>= 1)
                rs += __shfl_xor_sync(0xffffffffu, rs, off);
            l_i[i] = l_i[i] * scale + rs;
            m_i[i] = mnew;
#pragma unroll
            for (int j = 0; j < 4; ++j) o[i][j] *= scale;
            *(float4*)(Ps + (ty * 4 + i) * 68 + tx * 4) =
                make_float4(s[i][0], s[i][1], s[i][2], s[i][3]);
        }
        __syncthreads();

#pragma unroll 4
        for (int c = 0; c < 64; ++c) {
            float pv[4], vv[4];
#pragma unroll
            for (int i = 0; i < 4; ++i) pv[i] = Ps[(ty * 4 + i) * 68 + c];
#pragma unroll
            for (int j = 0; j < 4; ++j) vv[j] = Vs[c * 64 + tx * 4 + j];
#pragma unroll
            for (int i = 0; i < 4; ++i)
#pragma unroll
                for (int j = 0; j < 4; ++j)
                    o[i][j] += pv[i] * vv[j];
        }
    }

#pragma unroll
    for (int i = 0; i < 4; ++i) {
        int q = qt * 64 + ty * 4 + i;
        float inv = 1.f / l_i[i];
        float4 v = make_float4(o[i][0] * inv, o[i][1] * inv,
                               o[i][2] * inv, o[i][3] * inv);
        *(float4*)(g_O + ((size_t)(b * SEQ + q)) * EMB + h * HD + tx * 4) = v;
    }
}

// ---------------------------------------------------------------------------
extern "C" void kernel_launch(void* const* d_in, const int* in_sizes, int n_in,
                              void* d_out, int out_size)
{
    const float* Re  = (const float*)d_in[0];
    const float* Im  = (const float*)d_in[1];
    const float* pos = (const float*)d_in[2];
    const float* Wq  = (const float*)d_in[3];
    const float* bq  = (const float*)d_in[4];
    const float* Wk  = (const float*)d_in[5];
    const float* bk  = (const float*)d_in[6];
    const float* Wv  = (const float*)d_in[7];
    const float* bv  = (const float*)d_in[8];
    const float* Wo  = (const float*)d_in[9];
    const float* bo  = (const float*)d_in[10];
    float* out = (float*)d_out;

    static bool attrs_set = false;
    if (!attrs_set) {
        cudaFuncSetAttribute(gemm_tf32<0>, cudaFuncAttributeMaxDynamicSharedMemorySize, GEMM_SMEM);
        cudaFuncSetAttribute(gemm_tf32<1>, cudaFuncAttributeMaxDynamicSharedMemorySize, GEMM_SMEM);
        cudaFuncSetAttribute(gemm_tf32<2>, cudaFuncAttributeMaxDynamicSharedMemorySize, GEMM_SMEM);
        cudaFuncSetAttribute(gemm_tf32<3>, cudaFuncAttributeMaxDynamicSharedMemorySize, GEMM_SMEM);
        cudaFuncSetAttribute(attn_kernel, cudaFuncAttributeMaxDynamicSharedMemorySize,
                             (2 * 64 * 129 + 64 * 64 + 64 * 68) * (int)sizeof(float));
        attrs_set = true;
    }

    const dim3 gg(EMB / 128, M_TOT / 128);   // (8, 32)

    gemm_tf32<0><<<gg, 256, GEMM_SMEM>>>(Re, Wq, bq, pos, nullptr);
    gemm_tf32<1><<<gg, 256, GEMM_SMEM>>>(Re, Wk, bk, pos, nullptr);
    gemm_tf32<2><<<gg, 256, GEMM_SMEM>>>(Re, Wv, bv, pos, nullptr);
    im_fill_kernel<<<4096, 256>>>(Im);

    const int attn_smem = (2 * 64 * 129 + 64 * 64 + 64 * 68) * (int)sizeof(float); // 99840
    attn_kernel<<<dim3(16, NH, BATCH), 256, attn_smem>>>();

    gemm_tf32<3><<<gg, 256, GEMM_SMEM>>>(nullptr, Wo, bo, nullptr, out);
}

// round 6
// speedup vs baseline: 3.3547x; 2.1924x over previous
#include <cuda_runtime.h>
#include <cstdint>
#include <math.h>

#define BATCH 4
#define SEQ   1024
#define EMB   1024
#define NH    16
#define HD    64
#define M_TOT (BATCH*SEQ)          // 4096
#define INV_DENOM (1.0f/32.0f)     // 1/sqrt(EMB_DIM)

// Scratch (allocation-free: __device__ globals)
// NOTE: g_QA/g_KA/g_V hold tf32-ROUNDED fp32 bit patterns (mma-ready).
static __device__ float g_QA[BATCH*NH*SEQ*128];  // [b,h,s, 0:64]=(Q+P)/32, [64:128]=Im/32
static __device__ float g_KA[BATCH*NH*SEQ*128];  // [b,h,s, 0:64]=(K+P),   [64:128]=Im
static __device__ float g_V [BATCH*NH*SEQ*HD];   // [b,h,s,d] = (V+P)
static __device__ float g_O [M_TOT*EMB];         // merged-head attention output (full fp32)

// ---------------------------------------------------------------------------
// tf32 helpers
// ---------------------------------------------------------------------------
__device__ __forceinline__ uint32_t f2tf32(float f) {
    uint32_t u;
    asm("cvt.rna.tf32.f32 %0, %1;" : "=r"(u) : "f"(f));
    return u;
}

__device__ __forceinline__ void mma_tf32(float c[4], const uint32_t a[4],
                                         const uint32_t b[2]) {
    asm volatile(
        "mma.sync.aligned.m16n8k8.row.col.f32.tf32.tf32.f32 "
        "{%0,%1,%2,%3}, {%4,%5,%6,%7}, {%8,%9}, {%0,%1,%2,%3};"
        : "+f"(c[0]), "+f"(c[1]), "+f"(c[2]), "+f"(c[3])
        : "r"(a[0]), "r"(a[1]), "r"(a[2]), "r"(a[3]), "r"(b[0]), "r"(b[1]));
}

__device__ __forceinline__ void cp16(float* dst, const float* src) {
    uint32_t d = (uint32_t)__cvta_generic_to_shared(dst);
    asm volatile("cp.async.cg.shared.global [%0], [%1], 16;" :: "r"(d), "l"(src));
}

// ---------------------------------------------------------------------------
// TF32 GEMM: C = A[4096x1024] @ B[1024x1024], templated epilogue (as R5).
// ---------------------------------------------------------------------------
#define AS_STRIDE 36
#define BS_STRIDE 136
#define AS_WORDS  (128*AS_STRIDE)
#define BS_WORDS  (32*BS_STRIDE)
#define GEMM_SMEM ((2*AS_WORDS + 2*BS_WORDS)*4)   // 71680 bytes

template<int MODE>
__device__ __forceinline__ void gemm_store(int row, int col, float v,
    const float* __restrict__ bias, const float* __restrict__ pos,
    float* __restrict__ Out)
{
    v += bias[col];
    if (MODE <= 2) {
        const int bb = row >> 10, ss = row & 1023;
        const int h = col >> 6, d = col & 63;
        v += pos[(size_t)row * HD + d];
        const size_t hs = (size_t)((bb * NH + h) * SEQ + ss);
        if (MODE == 0)
            g_QA[hs * 128 + d] = __uint_as_float(f2tf32(v * INV_DENOM));
        else if (MODE == 1)
            g_KA[hs * 128 + d] = __uint_as_float(f2tf32(v));
        else
            g_V [hs * HD  + d] = __uint_as_float(f2tf32(v));
    } else {
        Out[(size_t)row * EMB + col] = v;
    }
}

template<int MODE>
__device__ __forceinline__ void issue_tile(
    const float* __restrict__ A, const float* __restrict__ Bm,
    float* as, float* bs, int t, int m0, int n0, int k0)
{
#pragma unroll
    for (int i = 0; i < 4; ++i) {
        int f = t + i * 256;
        int row = f >> 3, kc = (f & 7) * 4;
        cp16(as + row * AS_STRIDE + kc, A + (size_t)(m0 + row) * EMB + k0 + kc);
    }
#pragma unroll
    for (int i = 0; i < 4; ++i) {
        int f = t + i * 256;
        int k = f >> 5, nc = (f & 31) * 4;
        cp16(bs + k * BS_STRIDE + nc, Bm + (size_t)(k0 + k) * EMB + n0 + nc);
    }
    asm volatile("cp.async.commit_group;");
}

template<int MODE>
__global__ void __launch_bounds__(256, 2) gemm_tf32(
    const float* __restrict__ A, const float* __restrict__ Bm,
    const float* __restrict__ bias, const float* __restrict__ pos,
    float* __restrict__ Out)
{
    extern __shared__ float sm[];
    float* Asb[2] = { sm, sm + AS_WORDS };
    float* Bsb[2] = { sm + 2 * AS_WORDS, sm + 2 * AS_WORDS + BS_WORDS };

    const float* Ain = (MODE == 3) ? g_O : A;
    const int t    = threadIdx.x;
    const int m0   = blockIdx.y * 128;
    const int n0   = blockIdx.x * 128;
    const int lane = t & 31, warp = t >> 5;
    const int wm = warp >> 2, wn = warp & 3;

    float acc[4][4][4];
#pragma unroll
    for (int mf = 0; mf < 4; ++mf)
#pragma unroll
        for (int nf = 0; nf < 4; ++nf)
#pragma unroll
            for (int j = 0; j < 4; ++j) acc[mf][nf][j] = 0.f;

    issue_tile<MODE>(Ain, Bm, Asb[0], Bsb[0], t, m0, n0, 0);

    int cur = 0;
    for (int k0 = 0; k0 < EMB; k0 += 32) {
        const bool more = (k0 + 32 < EMB);
        if (more) {
            issue_tile<MODE>(Ain, Bm, Asb[cur ^ 1], Bsb[cur ^ 1], t, m0, n0, k0 + 32);
            asm volatile("cp.async.wait_group 1;");
        } else {
            asm volatile("cp.async.wait_group 0;");
        }
        __syncthreads();

        const float* as = Asb[cur];
        const float* bs = Bsb[cur];
#pragma unroll
        for (int kk = 0; kk < 32; kk += 8) {
            uint32_t a[4][4], b[4][2];
#pragma unroll
            for (int mf = 0; mf < 4; ++mf) {
                const float* p = as + (wm * 64 + mf * 16 + (lane >> 2)) * AS_STRIDE
                                    + kk + (lane & 3);
                a[mf][0] = f2tf32(p[0]);
                a[mf][1] = f2tf32(p[8 * AS_STRIDE]);
                a[mf][2] = f2tf32(p[4]);
                a[mf][3] = f2tf32(p[8 * AS_STRIDE + 4]);
            }
#pragma unroll
            for (int nf = 0; nf < 4; ++nf) {
                const float* p = bs + (kk + (lane & 3)) * BS_STRIDE
                                    + wn * 32 + nf * 8 + (lane >> 2);
                b[nf][0] = f2tf32(p[0]);
                b[nf][1] = f2tf32(p[4 * BS_STRIDE]);
            }
#pragma unroll
            for (int mf = 0; mf < 4; ++mf)
#pragma unroll
                for (int nf = 0; nf < 4; ++nf)
                    mma_tf32(acc[mf][nf], a[mf], b[nf]);
        }
        __syncthreads();
        cur ^= 1;
    }

#pragma unroll
    for (int mf = 0; mf < 4; ++mf) {
        const int r0 = m0 + wm * 64 + mf * 16 + (lane >> 2);
#pragma unroll
        for (int nf = 0; nf < 4; ++nf) {
            const int c0 = n0 + wn * 32 + nf * 8 + (lane & 3) * 2;
            gemm_store<MODE>(r0,     c0,     acc[mf][nf][0], bias, pos, Out);
            gemm_store<MODE>(r0,     c0 + 1, acc[mf][nf][1], bias, pos, Out);
            gemm_store<MODE>(r0 + 8, c0,     acc[mf][nf][2], bias, pos, Out);
            gemm_store<MODE>(r0 + 8, c0 + 1, acc[mf][nf][3], bias, pos, Out);
        }
    }
}

// ---------------------------------------------------------------------------
// Fill Im halves of augmented Q/K buffers (tf32-rounded)
// ---------------------------------------------------------------------------
__global__ void im_fill_kernel(const float* __restrict__ Im)
{
    int i = blockIdx.x * 256 + threadIdx.x;      // float4 units
    int d4 = (i & 15) * 4;
    int s  = (i >> 4) & 1023;
    int h  = (i >> 14) & 15;
    int b  = i >> 18;
    float4 v = *(const float4*)&Im[((size_t)(b * SEQ + s)) * EMB + h * HD + d4];
    size_t o = ((size_t)((b * NH + h) * SEQ + s)) * 128 + 64 + d4;
    float4 q;
    q.x = __uint_as_float(f2tf32(v.x * INV_DENOM));
    q.y = __uint_as_float(f2tf32(v.y * INV_DENOM));
    q.z = __uint_as_float(f2tf32(v.z * INV_DENOM));
    q.w = __uint_as_float(f2tf32(v.w * INV_DENOM));
    float4 k;
    k.x = __uint_as_float(f2tf32(v.x));
    k.y = __uint_as_float(f2tf32(v.y));
    k.z = __uint_as_float(f2tf32(v.z));
    k.w = __uint_as_float(f2tf32(v.w));
    *(float4*)&g_QA[o] = q;
    *(float4*)&g_KA[o] = k;
}

// ---------------------------------------------------------------------------
// TF32 MMA flash attention.
// 64 queries/CTA, 128 threads (4 warps x 16 rows). 16 key tiles of 64.
// Q fragments register-resident (k=128 -> 16 ksteps). K/V via cp.async.
// Online softmax on accumulator fragments; P through warp-private smem rows.
// Smem: Ks[64][132] (aliases Q stage), Vs[64][72], Ps[64][68].
// ---------------------------------------------------------------------------
#define ATT_SMEM ((64*132 + 64*72 + 64*68) * 4)   // 69632 bytes

__global__ void __launch_bounds__(128, 2) attn_mma()
{
    extern __shared__ float smA[];
    float* Ks = smA;                 // [64][132]  (Q staging first, then K tiles)
    float* Vs = smA + 64 * 132;      // [64][72]
    float* Ps = Vs + 64 * 72;        // [64][68]

    const int t    = threadIdx.x;
    const int lane = t & 31, warp = t >> 5;
    const int gid  = lane >> 2, tid = lane & 3;
    const int qt = blockIdx.x, h = blockIdx.y, b = blockIdx.z;
    const size_t head = (size_t)(b * NH + h);
    const float* Qg = g_QA + head * SEQ * 128 + (size_t)qt * 64 * 128;
    const float* Kg = g_KA + head * SEQ * 128;
    const float* Vg = g_V  + head * SEQ * HD;

    // Stage Q tile (64x128) into Ks buffer
#pragma unroll
    for (int i = 0; i < 16; ++i) {
        int f = t + i * 128;
        int r = f >> 5, c4 = (f & 31) * 4;
        cp16(Ks + r * 132 + c4, Qg + r * 128 + c4);
    }
    asm volatile("cp.async.commit_group;");
    asm volatile("cp.async.wait_group 0;");
    __syncthreads();

    // Q fragments (data already tf32 bits)
    uint32_t aQ[16][4];
    const int r0 = warp * 16 + gid;
#pragma unroll
    for (int ks = 0; ks < 16; ++ks) {
        aQ[ks][0] = __float_as_uint(Ks[r0 * 132 + ks * 8 + tid]);
        aQ[ks][1] = __float_as_uint(Ks[(r0 + 8) * 132 + ks * 8 + tid]);
        aQ[ks][2] = __float_as_uint(Ks[r0 * 132 + ks * 8 + tid + 4]);
        aQ[ks][3] = __float_as_uint(Ks[(r0 + 8) * 132 + ks * 8 + tid + 4]);
    }

    float m0v = -1e30f, m1v = -1e30f, l0 = 0.f, l1 = 0.f;
    float oAcc[8][4];
#pragma unroll
    for (int nf = 0; nf < 8; ++nf)
#pragma unroll
        for (int j = 0; j < 4; ++j) oAcc[nf][j] = 0.f;

    for (int kt = 0; kt < 16; ++kt) {
        __syncthreads();   // previous tile's reads of Ks/Vs done (kt=0: aQ loads done)
#pragma unroll
        for (int i = 0; i < 16; ++i) {
            int f = t + i * 128;
            int r = f >> 5, c4 = (f & 31) * 4;
            cp16(Ks + r * 132 + c4, Kg + (size_t)(kt * 64 + r) * 128 + c4);
        }
#pragma unroll
        for (int i = 0; i < 8; ++i) {
            int f = t + i * 128;
            int r = f >> 4, c4 = (f & 15) * 4;
            cp16(Vs + r * 72 + c4, Vg + (size_t)(kt * 64 + r) * HD + c4);
        }
        asm volatile("cp.async.commit_group;");
        asm volatile("cp.async.wait_group 0;");
        __syncthreads();

        // S = Q K^T  (16x64 per warp)
        float sS[8][4];
#pragma unroll
        for (int nf = 0; nf < 8; ++nf)
#pragma unroll
            for (int j = 0; j < 4; ++j) sS[nf][j] = 0.f;
#pragma unroll
        for (int ks = 0; ks < 16; ++ks) {
#pragma unroll
            for (int nf = 0; nf < 8; ++nf) {
                uint32_t b2[2];
                const float* kp = Ks + (nf * 8 + gid) * 132 + ks * 8 + tid;
                b2[0] = __float_as_uint(kp[0]);
                b2[1] = __float_as_uint(kp[4]);
                mma_tf32(sS[nf], aQ[ks], b2);
            }
        }

        // Online softmax: thread owns rows r0 (regs 0,1) and r0+8 (regs 2,3)
        float mx0 = -1e30f, mx1 = -1e30f;
#pragma unroll
        for (int nf = 0; nf < 8; ++nf) {
            mx0 = fmaxf(mx0, fmaxf(sS[nf][0], sS[nf][1]));
            mx1 = fmaxf(mx1, fmaxf(sS[nf][2], sS[nf][3]));
        }
#pragma unroll
        for (int off = 1; off <= 2; off <<= 1) {
            mx0 = fmaxf(mx0, __shfl_xor_sync(0xffffffffu, mx0, off));
            mx1 = fmaxf(mx1, __shfl_xor_sync(0xffffffffu, mx1, off));
        }
        const float mn0 = fmaxf(m0v, mx0), mn1 = fmaxf(m1v, mx1);
        const float sc0 = __expf(m0v - mn0), sc1 = __expf(m1v - mn1);
        float rs0 = 0.f, rs1 = 0.f;
#pragma unroll
        for (int nf = 0; nf < 8; ++nf) {
            sS[nf][0] = __expf(sS[nf][0] - mn0);
            sS[nf][1] = __expf(sS[nf][1] - mn0);
            sS[nf][2] = __expf(sS[nf][2] - mn1);
            sS[nf][3] = __expf(sS[nf][3] - mn1);
            rs0 += sS[nf][0] + sS[nf][1];
            rs1 += sS[nf][2] + sS[nf][3];
        }
#pragma unroll
        for (int off = 1; off <= 2; off <<= 1) {
            rs0 += __shfl_xor_sync(0xffffffffu, rs0, off);
            rs1 += __shfl_xor_sync(0xffffffffu, rs1, off);
        }
        l0 = l0 * sc0 + rs0;
        l1 = l1 * sc1 + rs1;
        m0v = mn0; m1v = mn1;
#pragma unroll
        for (int nf = 0; nf < 8; ++nf) {
            oAcc[nf][0] *= sc0; oAcc[nf][1] *= sc0;
            oAcc[nf][2] *= sc1; oAcc[nf][3] *= sc1;
            *(float2*)(Ps + r0 * 68 + nf * 8 + 2 * tid) =
                make_float2(sS[nf][0], sS[nf][1]);
            *(float2*)(Ps + (r0 + 8) * 68 + nf * 8 + 2 * tid) =
                make_float2(sS[nf][2], sS[nf][3]);
        }
        __syncwarp();   // Ps rows are warp-private; warp-level visibility suffices

        // O += P @ V   (keys = contraction dim, 8 ksteps)
#pragma unroll
        for (int ks = 0; ks < 8; ++ks) {
            uint32_t aP[4];
            const float* pp = Ps + r0 * 68 + ks * 8 + tid;
            aP[0] = f2tf32(pp[0]);
            aP[1] = f2tf32(pp[8 * 68]);
            aP[2] = f2tf32(pp[4]);
            aP[3] = f2tf32(pp[8 * 68 + 4]);
#pragma unroll
            for (int nf = 0; nf < 8; ++nf) {
                uint32_t b2[2];
                const float* vp = Vs + (ks * 8 + tid) * 72 + nf * 8 + gid;
                b2[0] = __float_as_uint(vp[0]);
                b2[1] = __float_as_uint(vp[4 * 72]);
                mma_tf32(oAcc[nf], aP, b2);
            }
        }
    }

    // Finalize: normalize and write merged-head layout
    const float i0 = 1.f / l0, i1 = 1.f / l1;
    const int q0 = qt * 64 + r0;
#pragma unroll
    for (int nf = 0; nf < 8; ++nf) {
        const int col = h * HD + nf * 8 + 2 * tid;
        *(float2*)(g_O + (size_t)(b * SEQ + q0) * EMB + col) =
            make_float2(oAcc[nf][0] * i0, oAcc[nf][1] * i0);
        *(float2*)(g_O + (size_t)(b * SEQ + q0 + 8) * EMB + col) =
            make_float2(oAcc[nf][2] * i1, oAcc[nf][3] * i1);
    }
}

// ---------------------------------------------------------------------------
extern "C" void kernel_launch(void* const* d_in, const int* in_sizes, int n_in,
                              void* d_out, int out_size)
{
    const float* Re  = (const float*)d_in[0];
    const float* Im  = (const float*)d_in[1];
    const float* pos = (const float*)d_in[2];
    const float* Wq  = (const float*)d_in[3];
    const float* bq  = (const float*)d_in[4];
    const float* Wk  = (const float*)d_in[5];
    const float* bk  = (const float*)d_in[6];
    const float* Wv  = (const float*)d_in[7];
    const float* bv  = (const float*)d_in[8];
    const float* Wo  = (const float*)d_in[9];
    const float* bo  = (const float*)d_in[10];
    float* out = (float*)d_out;

    static bool attrs_set = false;
    if (!attrs_set) {
        cudaFuncSetAttribute(gemm_tf32<0>, cudaFuncAttributeMaxDynamicSharedMemorySize, GEMM_SMEM);
        cudaFuncSetAttribute(gemm_tf32<1>, cudaFuncAttributeMaxDynamicSharedMemorySize, GEMM_SMEM);
        cudaFuncSetAttribute(gemm_tf32<2>, cudaFuncAttributeMaxDynamicSharedMemorySize, GEMM_SMEM);
        cudaFuncSetAttribute(gemm_tf32<3>, cudaFuncAttributeMaxDynamicSharedMemorySize, GEMM_SMEM);
        cudaFuncSetAttribute(attn_mma,     cudaFuncAttributeMaxDynamicSharedMemorySize, ATT_SMEM);
        attrs_set = true;
    }

    const dim3 gg(EMB / 128, M_TOT / 128);   // (8, 32)

    gemm_tf32<0><<<gg, 256, GEMM_SMEM>>>(Re, Wq, bq, pos, nullptr);
    gemm_tf32<1><<<gg, 256, GEMM_SMEM>>>(Re, Wk, bk, pos, nullptr);
    gemm_tf32<2><<<gg, 256, GEMM_SMEM>>>(Re, Wv, bv, pos, nullptr);
    im_fill_kernel<<<4096, 256>>>(Im);

    attn_mma<<<dim3(16, NH, BATCH), 128, ATT_SMEM>>>();

    gemm_tf32<3><<<gg, 256, GEMM_SMEM>>>(nullptr, Wo, bo, nullptr, out);
}

// round 7
// speedup vs baseline: 3.4624x; 1.0321x over previous
#include <cuda_runtime.h>
#include <cstdint>
#include <math.h>

#define BATCH 4
#define SEQ   1024
#define EMB   1024
#define NH    16
#define HD    64
#define M_TOT (BATCH*SEQ)          // 4096
#define INV_DENOM (1.0f/32.0f)     // 1/sqrt(EMB_DIM)

// Scratch (allocation-free: __device__ globals). All mma-operand buffers hold
// tf32-ROUNDED fp32 bit patterns so mainloops do raw LDS (no CVT).
static __device__ float g_QA[BATCH*NH*SEQ*128];  // [b,h,s, 0:64]=(Q+P)/32, [64:128]=Im/32
static __device__ float g_KA[BATCH*NH*SEQ*128];  // [b,h,s, 0:64]=(K+P),   [64:128]=Im
static __device__ float g_V [BATCH*NH*SEQ*HD];   // (V+P), tf32-rounded
static __device__ float g_O [M_TOT*EMB];         // attention out, tf32-rounded
static __device__ float g_Re[M_TOT*EMB];         // Re, tf32-rounded
static __device__ float g_W [4*EMB*EMB];         // Wq|Wk|Wv|Wo, tf32-rounded

// ---------------------------------------------------------------------------
__device__ __forceinline__ uint32_t f2tf32(float f) {
    uint32_t u;
    asm("cvt.rna.tf32.f32 %0, %1;" : "=r"(u) : "f"(f));
    return u;
}
__device__ __forceinline__ float rtf(float f) { return __uint_as_float(f2tf32(f)); }

__device__ __forceinline__ void mma_tf32(float c[4], const uint32_t a[4],
                                         const uint32_t b[2]) {
    asm volatile(
        "mma.sync.aligned.m16n8k8.row.col.f32.tf32.tf32.f32 "
        "{%0,%1,%2,%3}, {%4,%5,%6,%7}, {%8,%9}, {%0,%1,%2,%3};"
        : "+f"(c[0]), "+f"(c[1]), "+f"(c[2]), "+f"(c[3])
        : "r"(a[0]), "r"(a[1]), "r"(a[2]), "r"(a[3]), "r"(b[0]), "r"(b[1]));
}

__device__ __forceinline__ void cp16(float* dst, const float* src) {
    uint32_t d = (uint32_t)__cvta_generic_to_shared(dst);
    asm volatile("cp.async.cg.shared.global [%0], [%1], 16;" :: "r"(d), "l"(src));
}

// ---------------------------------------------------------------------------
// Pre-round a float buffer to tf32 bit patterns (vectorized).
// ---------------------------------------------------------------------------
__global__ void round_tf32_kernel(const float* __restrict__ src,
                                  float* __restrict__ dst, int n4)
{
    int i = blockIdx.x * 256 + threadIdx.x;
    if (i < n4) {
        float4 v = ((const float4*)src)[i];
        v.x = rtf(v.x); v.y = rtf(v.y); v.z = rtf(v.z); v.w = rtf(v.w);
        ((float4*)dst)[i] = v;
    }
}

// ---------------------------------------------------------------------------
// TF32 GEMM: C = A[4096x1024] @ B[1024x1024]. CTA tile 128x256x32,
// 8 warps (2m x 4n), warp tile 64x64, m16n8k8. A/B pre-rounded -> raw LDS.
// Smem: A[128][36], B[32][264] (both bank-conflict-free). 2-stage cp.async.
// MODE 0: Q proj -> g_QA   MODE 1: K -> g_KA   MODE 2: V -> g_V   MODE 3: -> Out
// ---------------------------------------------------------------------------
#define AS_STRIDE 36
#define BS_STRIDE 264
#define AS_WORDS  (128*AS_STRIDE)   // 4608
#define BS_WORDS  (32*BS_STRIDE)    // 8448
#define GEMM_SMEM ((2*AS_WORDS + 2*BS_WORDS)*4)   // 104448 bytes

template<int MODE>
__device__ __forceinline__ void gemm_store(int row, int col, float v,
    const float* __restrict__ bias, const float* __restrict__ pos,
    float* __restrict__ Out)
{
    v += bias[col];
    if (MODE <= 2) {
        const int bb = row >> 10, ss = row & 1023;
        const int h = col >> 6, d = col & 63;
        v += pos[(size_t)row * HD + d];
        const size_t hs = (size_t)((bb * NH + h) * SEQ + ss);
        if (MODE == 0)      g_QA[hs * 128 + d] = rtf(v * INV_DENOM);
        else if (MODE == 1) g_KA[hs * 128 + d] = rtf(v);
        else                g_V [hs * HD  + d] = rtf(v);
    } else {
        Out[(size_t)row * EMB + col] = v;
    }
}

__device__ __forceinline__ void issue_tile256(
    const float* __restrict__ A, const float* __restrict__ Bm,
    float* as, float* bs, int t, int m0, int n0, int k0)
{
#pragma unroll
    for (int i = 0; i < 4; ++i) {          // A: 128 x 32
        int f = t + i * 256;
        int row = f >> 3, kc = (f & 7) * 4;
        cp16(as + row * AS_STRIDE + kc, A + (size_t)(m0 + row) * EMB + k0 + kc);
    }
#pragma unroll
    for (int i = 0; i < 8; ++i) {          // B: 32 x 256
        int f = t + i * 256;
        int k = f >> 6, nc = (f & 63) * 4;
        cp16(bs + k * BS_STRIDE + nc, Bm + (size_t)(k0 + k) * EMB + n0 + nc);
    }
    asm volatile("cp.async.commit_group;");
}

template<int MODE>
__global__ void __launch_bounds__(256, 1) gemm_tf32(
    const float* __restrict__ A, const float* __restrict__ Bm,
    const float* __restrict__ bias, const float* __restrict__ pos,
    float* __restrict__ Out)
{
    extern __shared__ float sm[];
    float* Asb[2] = { sm, sm + AS_WORDS };
    float* Bsb[2] = { sm + 2 * AS_WORDS, sm + 2 * AS_WORDS + BS_WORDS };

    const int t    = threadIdx.x;
    const int m0   = blockIdx.y * 128;
    const int n0   = blockIdx.x * 256;
    const int lane = t & 31, warp = t >> 5;
    const int gid  = lane >> 2, tid = lane & 3;
    const int wm = warp >> 2, wn = warp & 3;

    float acc[4][8][4];
#pragma unroll
    for (int mf = 0; mf < 4; ++mf)
#pragma unroll
        for (int nf = 0; nf < 8; ++nf)
#pragma unroll
            for (int j = 0; j < 4; ++j) acc[mf][nf][j] = 0.f;

    issue_tile256(A, Bm, Asb[0], Bsb[0], t, m0, n0, 0);

    int cur = 0;
    for (int k0 = 0; k0 < EMB; k0 += 32) {
        if (k0 + 32 < EMB) {
            issue_tile256(A, Bm, Asb[cur ^ 1], Bsb[cur ^ 1], t, m0, n0, k0 + 32);
            asm volatile("cp.async.wait_group 1;");
        } else {
            asm volatile("cp.async.wait_group 0;");
        }
        __syncthreads();

        const float* as = Asb[cur];
        const float* bs = Bsb[cur];
#pragma unroll
        for (int kk = 0; kk < 32; kk += 8) {
            uint32_t a[4][4], b[8][2];
#pragma unroll
            for (int mf = 0; mf < 4; ++mf) {
                const float* p = as + (wm * 64 + mf * 16 + gid) * AS_STRIDE + kk + tid;
                a[mf][0] = __float_as_uint(p[0]);
                a[mf][1] = __float_as_uint(p[8 * AS_STRIDE]);
                a[mf][2] = __float_as_uint(p[4]);
                a[mf][3] = __float_as_uint(p[8 * AS_STRIDE + 4]);
            }
#pragma unroll
            for (int nf = 0; nf < 8; ++nf) {
                const float* p = bs + (kk + tid) * BS_STRIDE + wn * 64 + nf * 8 + gid;
                b[nf][0] = __float_as_uint(p[0]);
                b[nf][1] = __float_as_uint(p[4 * BS_STRIDE]);
            }
#pragma unroll
            for (int mf = 0; mf < 4; ++mf)
#pragma unroll
                for (int nf = 0; nf < 8; ++nf)
                    mma_tf32(acc[mf][nf], a[mf], b[nf]);
        }
        __syncthreads();
        cur ^= 1;
    }

#pragma unroll
    for (int mf = 0; mf < 4; ++mf) {
        const int r0 = m0 + wm * 64 + mf * 16 + gid;
#pragma unroll
        for (int nf = 0; nf < 8; ++nf) {
            const int c0 = n0 + wn * 64 + nf * 8 + tid * 2;
            gemm_store<MODE>(r0,     c0,     acc[mf][nf][0], bias, pos, Out);
            gemm_store<MODE>(r0,     c0 + 1, acc[mf][nf][1], bias, pos, Out);
            gemm_store<MODE>(r0 + 8, c0,     acc[mf][nf][2], bias, pos, Out);
            gemm_store<MODE>(r0 + 8, c0 + 1, acc[mf][nf][3], bias, pos, Out);
        }
    }
}

// ---------------------------------------------------------------------------
// Fill Im halves of augmented Q/K buffers (tf32-rounded)
// ---------------------------------------------------------------------------
__global__ void im_fill_kernel(const float* __restrict__ Im)
{
    int i = blockIdx.x * 256 + threadIdx.x;      // float4 units
    int d4 = (i & 15) * 4;
    int s  = (i >> 4) & 1023;
    int h  = (i >> 14) & 15;
    int b  = i >> 18;
    float4 v = *(const float4*)&Im[((size_t)(b * SEQ + s)) * EMB + h * HD + d4];
    size_t o = ((size_t)((b * NH + h) * SEQ + s)) * 128 + 64 + d4;
    float4 q = make_float4(rtf(v.x * INV_DENOM), rtf(v.y * INV_DENOM),
                           rtf(v.z * INV_DENOM), rtf(v.w * INV_DENOM));
    float4 k = make_float4(rtf(v.x), rtf(v.y), rtf(v.z), rtf(v.w));
    *(float4*)&g_QA[o] = q;
    *(float4*)&g_KA[o] = k;
}

// ---------------------------------------------------------------------------
// TF32 MMA flash attention (as R6; g_O stored tf32-rounded).
// ---------------------------------------------------------------------------
#define ATT_SMEM ((64*132 + 64*72 + 64*68) * 4)   // 69632 bytes

__global__ void __launch_bounds__(128, 2) attn_mma()
{
    extern __shared__ float smA[];
    float* Ks = smA;                 // [64][132]
    float* Vs = smA + 64 * 132;      // [64][72]
    float* Ps = Vs + 64 * 72;        // [64][68]

    const int t    = threadIdx.x;
    const int lane = t & 31, warp = t >> 5;
    const int gid  = lane >> 2, tid = lane & 3;
    const int qt = blockIdx.x, h = blockIdx.y, b = blockIdx.z;
    const size_t head = (size_t)(b * NH + h);
    const float* Qg = g_QA + head * SEQ * 128 + (size_t)qt * 64 * 128;
    const float* Kg = g_KA + head * SEQ * 128;
    const float* Vg = g_V  + head * SEQ * HD;

#pragma unroll
    for (int i = 0; i < 16; ++i) {
        int f = t + i * 128;
        int r = f >> 5, c4 = (f & 31) * 4;
        cp16(Ks + r * 132 + c4, Qg + r * 128 + c4);
    }
    asm volatile("cp.async.commit_group;");
    asm volatile("cp.async.wait_group 0;");
    __syncthreads();

    uint32_t aQ[16][4];
    const int r0 = warp * 16 + gid;
#pragma unroll
    for (int ks = 0; ks < 16; ++ks) {
        aQ[ks][0] = __float_as_uint(Ks[r0 * 132 + ks * 8 + tid]);
        aQ[ks][1] = __float_as_uint(Ks[(r0 + 8) * 132 + ks * 8 + tid]);
        aQ[ks][2] = __float_as_uint(Ks[r0 * 132 + ks * 8 + tid + 4]);
        aQ[ks][3] = __float_as_uint(Ks[(r0 + 8) * 132 + ks * 8 + tid + 4]);
    }

    float m0v = -1e30f, m1v = -1e30f, l0 = 0.f, l1 = 0.f;
    float oAcc[8][4];
#pragma unroll
    for (int nf = 0; nf < 8; ++nf)
#pragma unroll
        for (int j = 0; j < 4; ++j) oAcc[nf][j] = 0.f;

    for (int kt = 0; kt < 16; ++kt) {
        __syncthreads();
#pragma unroll
        for (int i = 0; i < 16; ++i) {
            int f = t + i * 128;
            int r = f >> 5, c4 = (f & 31) * 4;
            cp16(Ks + r * 132 + c4, Kg + (size_t)(kt * 64 + r) * 128 + c4);
        }
#pragma unroll
        for (int i = 0; i < 8; ++i) {
            int f = t + i * 128;
            int r = f >> 4, c4 = (f & 15) * 4;
            cp16(Vs + r * 72 + c4, Vg + (size_t)(kt * 64 + r) * HD + c4);
        }
        asm volatile("cp.async.commit_group;");
        asm volatile("cp.async.wait_group 0;");
        __syncthreads();

        float sS[8][4];
#pragma unroll
        for (int nf = 0; nf < 8; ++nf)
#pragma unroll
            for (int j = 0; j < 4; ++j) sS[nf][j] = 0.f;
#pragma unroll
        for (int ks = 0; ks < 16; ++ks) {
#pragma unroll
            for (int nf = 0; nf < 8; ++nf) {
                uint32_t b2[2];
                const float* kp = Ks + (nf * 8 + gid) * 132 + ks * 8 + tid;
                b2[0] = __float_as_uint(kp[0]);
                b2[1] = __float_as_uint(kp[4]);
                mma_tf32(sS[nf], aQ[ks], b2);
            }
        }

        float mx0 = -1e30f, mx1 = -1e30f;
#pragma unroll
        for (int nf = 0; nf < 8; ++nf) {
            mx0 = fmaxf(mx0, fmaxf(sS[nf][0], sS[nf][1]));
            mx1 = fmaxf(mx1, fmaxf(sS[nf][2], sS[nf][3]));
        }
#pragma unroll
        for (int off = 1; off <= 2; off <<= 1) {
            mx0 = fmaxf(mx0, __shfl_xor_sync(0xffffffffu, mx0, off));
            mx1 = fmaxf(mx1, __shfl_xor_sync(0xffffffffu, mx1, off));
        }
        const float mn0 = fmaxf(m0v, mx0), mn1 = fmaxf(m1v, mx1);
        const float sc0 = __expf(m0v - mn0), sc1 = __expf(m1v - mn1);
        float rs0 = 0.f, rs1 = 0.f;
#pragma unroll
        for (int nf = 0; nf < 8; ++nf) {
            sS[nf][0] = __expf(sS[nf][0] - mn0);
            sS[nf][1] = __expf(sS[nf][1] - mn0);
            sS[nf][2] = __expf(sS[nf][2] - mn1);
            sS[nf][3] = __expf(sS[nf][3] - mn1);
            rs0 += sS[nf][0] + sS[nf][1];
            rs1 += sS[nf][2] + sS[nf][3];
        }
#pragma unroll
        for (int off = 1; off <= 2; off <<= 1) {
            rs0 += __shfl_xor_sync(0xffffffffu, rs0, off);
            rs1 += __shfl_xor_sync(0xffffffffu, rs1, off);
        }
        l0 = l0 * sc0 + rs0;
        l1 = l1 * sc1 + rs1;
        m0v = mn0; m1v = mn1;
#pragma unroll
        for (int nf = 0; nf < 8; ++nf) {
            oAcc[nf][0] *= sc0; oAcc[nf][1] *= sc0;
            oAcc[nf][2] *= sc1; oAcc[nf][3] *= sc1;
            *(float2*)(Ps + r0 * 68 + nf * 8 + 2 * tid) =
                make_float2(sS[nf][0], sS[nf][1]);
            *(float2*)(Ps + (r0 + 8) * 68 + nf * 8 + 2 * tid) =
                make_float2(sS[nf][2], sS[nf][3]);
        }
        __syncwarp();

#pragma unroll
        for (int ks = 0; ks < 8; ++ks) {
            uint32_t aP[4];
            const float* pp = Ps + r0 * 68 + ks * 8 + tid;
            aP[0] = f2tf32(pp[0]);
            aP[1] = f2tf32(pp[8 * 68]);
            aP[2] = f2tf32(pp[4]);
            aP[3] = f2tf32(pp[8 * 68 + 4]);
#pragma unroll
            for (int nf = 0; nf < 8; ++nf) {
                uint32_t b2[2];
                const float* vp = Vs + (ks * 8 + tid) * 72 + nf * 8 + gid;
                b2[0] = __float_as_uint(vp[0]);
                b2[1] = __float_as_uint(vp[4 * 72]);
                mma_tf32(oAcc[nf], aP, b2);
            }
        }
    }

    const float i0 = 1.f / l0, i1 = 1.f / l1;
    const int q0 = qt * 64 + r0;
#pragma unroll
    for (int nf = 0; nf < 8; ++nf) {
        const int col = h * HD + nf * 8 + 2 * tid;
        *(float2*)(g_O + (size_t)(b * SEQ + q0) * EMB + col) =
            make_float2(rtf(oAcc[nf][0] * i0), rtf(oAcc[nf][1] * i0));
        *(float2*)(g_O + (size_t)(b * SEQ + q0 + 8) * EMB + col) =
            make_float2(rtf(oAcc[nf][2] * i1), rtf(oAcc[nf][3] * i1));
    }
}

// ---------------------------------------------------------------------------
extern "C" void kernel_launch(void* const* d_in, const int* in_sizes, int n_in,
                              void* d_out, int out_size)
{
    const float* Re  = (const float*)d_in[0];
    const float* Im  = (const float*)d_in[1];
    const float* pos = (const float*)d_in[2];
    const float* Wq  = (const float*)d_in[3];
    const float* bq  = (const float*)d_in[4];
    const float* Wk  = (const float*)d_in[5];
    const float* bk  = (const float*)d_in[6];
    const float* Wv  = (const float*)d_in[7];
    const float* bv  = (const float*)d_in[8];
    const float* Wo  = (const float*)d_in[9];
    const float* bo  = (const float*)d_in[10];
    float* out = (float*)d_out;

    float* gRe; cudaGetSymbolAddress((void**)&gRe, g_Re);
    float* gW;  cudaGetSymbolAddress((void**)&gW,  g_W);

    static bool attrs_set = false;
    if (!attrs_set) {
        cudaFuncSetAttribute(gemm_tf32<0>, cudaFuncAttributeMaxDynamicSharedMemorySize, GEMM_SMEM);
        cudaFuncSetAttribute(gemm_tf32<1>, cudaFuncAttributeMaxDynamicSharedMemorySize, GEMM_SMEM);
        cudaFuncSetAttribute(gemm_tf32<2>, cudaFuncAttributeMaxDynamicSharedMemorySize, GEMM_SMEM);
        cudaFuncSetAttribute(gemm_tf32<3>, cudaFuncAttributeMaxDynamicSharedMemorySize, GEMM_SMEM);
        cudaFuncSetAttribute(attn_mma,     cudaFuncAttributeMaxDynamicSharedMemorySize, ATT_SMEM);
        attrs_set = true;
    }

    // Pre-round operands to tf32 (removes all CVT from GEMM mainloops)
    const int W4 = EMB * EMB / 4;                 // 262144 float4
    round_tf32_kernel<<<(M_TOT * EMB / 4 + 255) / 256, 256>>>(Re, gRe, M_TOT * EMB / 4);
    round_tf32_kernel<<<(W4 + 255) / 256, 256>>>(Wq, gW + 0 * EMB * EMB, W4);
    round_tf32_kernel<<<(W4 + 255) / 256, 256>>>(Wk, gW + 1 * EMB * EMB, W4);
    round_tf32_kernel<<<(W4 + 255) / 256, 256>>>(Wv, gW + 2 * EMB * EMB, W4);
    round_tf32_kernel<<<(W4 + 255) / 256, 256>>>(Wo, gW + 3 * EMB * EMB, W4);

    const dim3 gg(EMB / 256, M_TOT / 128);   // (4, 32) = 128 CTAs

    gemm_tf32<0><<<gg, 256, GEMM_SMEM>>>(gRe, gW + 0 * EMB * EMB, bq, pos, nullptr);
    gemm_tf32<1><<<gg, 256, GEMM_SMEM>>>(gRe, gW + 1 * EMB * EMB, bk, pos, nullptr);
    gemm_tf32<2><<<gg, 256, GEMM_SMEM>>>(gRe, gW + 2 * EMB * EMB, bv, pos, nullptr);
    im_fill_kernel<<<4096, 256>>>(Im);

    attn_mma<<<dim3(16, NH, BATCH), 128, ATT_SMEM>>>();

    float* gO; cudaGetSymbolAddress((void**)&gO, g_O);
    gemm_tf32<3><<<gg, 256, GEMM_SMEM>>>(gO, gW + 3 * EMB * EMB, bo, nullptr, out);
}